// round 1
// baseline (speedup 1.0000x reference)
#include <cuda_runtime.h>
#include <cuda_bf16.h>
#include <math.h>

// ============================================================================
// CTC decoder:  finalP = f(log_softmax(x @ W^T + b), ctc recursion)
//
//   Kernel 1: init (out=LOGZERO, sumexp=0)
//   Kernel 2: fused f32x2 GEMM + exp-sum epilogue (atomicAdd partial sums)
//   Kernel 3: gather 31 dot products per row (blank + beams)
//   Kernel 4: per-batch CTC scan (logaddexp recursion over T)
//
// Algebraic notes:
//   * full logp never materialized: only per-row lse + 31 gathered logits.
//   * logits are tiny (std ~0.45) -> exp-sum without max subtraction is safe.
//   * logaddexp(LOGZERO, x) == x exactly in f32 -> lastPsum == lastP1, so the
//     `same`/`y` branch of the reference is a no-op and y is unused.
// ============================================================================

#define LOGZERO (-4290774016.0f)   // -(65504.0**2), exactly representable in f32

#define BM 128
#define BN 128
#define BK 32

__device__ float g_sumexp[32768];
__device__ float g_blank[32768];
__device__ float g_beam[32768 * 32];

__device__ __forceinline__ unsigned long long pack2(float x, float y) {
    unsigned long long r;
    asm("mov.b64 %0, {%1, %2};" : "=l"(r) : "f"(x), "f"(y));
    return r;
}
__device__ __forceinline__ void fma2(unsigned long long& d, unsigned long long a,
                                     unsigned long long b) {
    asm("fma.rn.f32x2 %0, %1, %2, %0;" : "+l"(d) : "l"(a), "l"(b));
}
__device__ __forceinline__ void unpack2(unsigned long long v, float& lo, float& hi) {
    asm("mov.b64 {%0, %1}, %2;" : "=f"(lo), "=f"(hi) : "l"(v));
}

__device__ __forceinline__ float laexp(float a, float b) {
    float m = fmaxf(a, b);
    float d = fminf(a, b) - m;
    return m + log1pf(expf(d));
}

// ---------------------------------------------------------------------------
__global__ void init_kernel(float* __restrict__ out, int outN, int M) {
    int i = blockIdx.x * blockDim.x + threadIdx.x;
    if (i < outN) out[i] = LOGZERO;
    if (i < M)    g_sumexp[i] = 0.0f;
}

// ---------------------------------------------------------------------------
// C[m,n] = sum_k X[m,k]*W[n,k] + bias[n];  g_sumexp[m] += sum_n exp(C[m,n])
// M,N multiples of 128; K multiple of 32.
// ---------------------------------------------------------------------------
__global__ __launch_bounds__(256, 2)
void gemm_lse_kernel(const float* __restrict__ X, const float* __restrict__ Wm,
                     const float* __restrict__ bias, int M, int N, int K) {
    __shared__ __align__(16) float As[BK][BM];
    __shared__ __align__(16) float Bs[BK][BN];

    const int bm = blockIdx.y * BM;
    const int bn = blockIdx.x * BN;
    const int tid = threadIdx.x;
    const int ty = tid >> 4;
    const int tx = tid & 15;
    const int trow = ty * 8;
    const int tcol = tx * 8;

    unsigned long long acc2[8][4];
#pragma unroll
    for (int r = 0; r < 8; r++)
#pragma unroll
        for (int c = 0; c < 4; c++) acc2[r][c] = 0ull;

    for (int k0 = 0; k0 < K; k0 += BK) {
#pragma unroll
        for (int i = 0; i < 4; i++) {
            int idx = tid + i * 256;
            int row = idx & 127;
            int kv  = idx >> 7;
            float4 va = *reinterpret_cast<const float4*>(
                X + (size_t)(bm + row) * K + k0 + (kv << 2));
            As[(kv << 2) + 0][row] = va.x;
            As[(kv << 2) + 1][row] = va.y;
            As[(kv << 2) + 2][row] = va.z;
            As[(kv << 2) + 3][row] = va.w;
            float4 vb = *reinterpret_cast<const float4*>(
                Wm + (size_t)(bn + row) * K + k0 + (kv << 2));
            Bs[(kv << 2) + 0][row] = vb.x;
            Bs[(kv << 2) + 1][row] = vb.y;
            Bs[(kv << 2) + 2][row] = vb.z;
            Bs[(kv << 2) + 3][row] = vb.w;
        }
        __syncthreads();

#pragma unroll
        for (int kk = 0; kk < BK; kk++) {
            float4 a0 = *reinterpret_cast<const float4*>(&As[kk][trow]);
            float4 a1 = *reinterpret_cast<const float4*>(&As[kk][trow + 4]);
            float4 w0 = *reinterpret_cast<const float4*>(&Bs[kk][tcol]);
            float4 w1 = *reinterpret_cast<const float4*>(&Bs[kk][tcol + 4]);
            unsigned long long wp0 = pack2(w0.x, w0.y);
            unsigned long long wp1 = pack2(w0.z, w0.w);
            unsigned long long wp2 = pack2(w1.x, w1.y);
            unsigned long long wp3 = pack2(w1.z, w1.w);
            float av[8] = {a0.x, a0.y, a0.z, a0.w, a1.x, a1.y, a1.z, a1.w};
#pragma unroll
            for (int r = 0; r < 8; r++) {
                unsigned long long ap = pack2(av[r], av[r]);
                fma2(acc2[r][0], ap, wp0);
                fma2(acc2[r][1], ap, wp1);
                fma2(acc2[r][2], ap, wp2);
                fma2(acc2[r][3], ap, wp3);
            }
        }
        __syncthreads();
    }

    float bv[8];
#pragma unroll
    for (int c = 0; c < 8; c++) bv[c] = bias[bn + tcol + c];

#pragma unroll
    for (int r = 0; r < 8; r++) {
        float s = 0.0f;
#pragma unroll
        for (int c = 0; c < 4; c++) {
            float lo, hi;
            unpack2(acc2[r][c], lo, hi);
            s += __expf(lo + bv[2 * c]) + __expf(hi + bv[2 * c + 1]);
        }
#pragma unroll
        for (int off = 8; off >= 1; off >>= 1)
            s += __shfl_xor_sync(0xffffffffu, s, off);
        if (tx == 0) atomicAdd(&g_sumexp[bm + trow + r], s);
    }
}

// ---------------------------------------------------------------------------
__global__ void gather_kernel(const float* __restrict__ X, const float* __restrict__ Wm,
                              const float* __restrict__ bias,
                              const int* __restrict__ beam, const int* __restrict__ blankp,
                              int T, int D, int CB) {
    const int row = blockIdx.x;          // b*T + t
    const int b = row / T;
    __shared__ float xs[1024];

    for (int i = threadIdx.x; i < D; i += blockDim.x)
        xs[i] = X[(size_t)row * D + i];
    __syncthreads();

    const int lane = threadIdx.x & 31;
    const int warp = threadIdx.x >> 5;
    const int nwarps = blockDim.x >> 5;
    const int blankv = blankp ? blankp[0] : 0;
    const int ncols = CB + 1;

    for (int j = warp; j < ncols; j += nwarps) {
        int col = (j == CB) ? blankv : beam[b * CB + j];
        const float* wr = Wm + (size_t)col * D;
        float s = 0.0f;
        for (int i = lane; i < D; i += 32) s += xs[i] * wr[i];
#pragma unroll
        for (int off = 16; off >= 1; off >>= 1)
            s += __shfl_xor_sync(0xffffffffu, s, off);
        if (lane == 0) {
            float val = s + bias[col];
            if (j == CB) g_blank[row] = val;
            else         g_beam[(size_t)row * CB + j] = val;
        }
    }
}

// ---------------------------------------------------------------------------
__global__ void scan_kernel(const int* __restrict__ xl, const int* __restrict__ beam,
                            const int* __restrict__ blankp, const int* __restrict__ eosp,
                            float* __restrict__ out, int T, int V, int CB, int Ly) {
    const int b = blockIdx.x;
    const int j = threadIdx.x;
    const int blankv = blankp ? blankp[0] : 0;
    const int eosv   = eosp ? eosp[0] : (V - 1);

    int start = Ly < (T - 1) ? Ly : (T - 1);
    int loop_start = start > 1 ? start : 1;
    const int xlb = xl[b];
    const bool active = (j < CB);

    float Pn = LOGZERO, Pb = LOGZERO, acc = LOGZERO;
    float cum = 0.0f, pref_prev = 0.0f, eosval = 0.0f;

    for (int t = 0; t < T; t++) {
        const int row = b * T + t;
        const float lse = logf(g_sumexp[row]);
        const float lpb = g_blank[row] - lse;
        cum = (t == 0) ? lpb : (cum + lpb);              // lastP1[t]

        if (active) {
            float xn = g_beam[(size_t)row * CB + j] - lse;
            if (t == 0 && start == 0) {
                Pn = xn;
                Pb = LOGZERO;
            } else if (t >= loop_start) {
                float pn_new = laexp(Pn, pref_prev) + xn;
                float pb_new = laexp(Pn, Pb) + lpb;
                Pn = pn_new;
                Pb = pb_new;
            }
            if (t >= start && t < xlb)
                acc = laexp(acc, laexp(Pn, Pb));
        }
        if (t == xlb - 1) eosval = cum;
        pref_prev = cum;
    }

    if (active) out[(size_t)b * V + beam[b * CB + j]] = acc;
    __syncthreads();
    if (j == 0) {
        out[(size_t)b * V + eosv]   = (xlb >= 1 && xlb <= T) ? eosval : 0.0f;
        out[(size_t)b * V + blankv] = LOGZERO;
    }
}

// ---------------------------------------------------------------------------
extern "C" void kernel_launch(void* const* d_in, const int* in_sizes, int n_in,
                              void* d_out, int out_size) {
    const float* x    = (const float*)d_in[0];   // (B,T,D)
    const float* W    = (const float*)d_in[1];   // (V,D)
    const float* bias = (const float*)d_in[2];   // (V,)
    const int*   xl   = (const int*)d_in[3];     // (B,)
    // d_in[4] = y : unused (prefP branch collapses, see header note)
    const int*   beam = (const int*)d_in[5];     // (B,CB)
    const int*   blankp = (n_in > 6) ? (const int*)d_in[6] : nullptr;
    const int*   eosp   = (n_in > 7) ? (const int*)d_in[7] : nullptr;

    const int B  = in_sizes[3];
    const int V  = in_sizes[2];
    const int D  = in_sizes[1] / V;
    const int T  = in_sizes[0] / (B * D);
    const int CB = in_sizes[5] / B;
    const int Ly = in_sizes[4] / B;
    const int M  = B * T;

    float* out = (float*)d_out;

    int initN = out_size > M ? out_size : M;
    init_kernel<<<(initN + 255) / 256, 256>>>(out, out_size, M);

    dim3 g2(V / BN, M / BM);
    gemm_lse_kernel<<<g2, 256>>>(x, W, bias, M, V, D);

    gather_kernel<<<M, 128>>>(x, W, bias, beam, blankp, T, D, CB);

    scan_kernel<<<B, 32>>>(xl, beam, blankp, eosp, out, T, V, CB, Ly);
}

// round 3
// speedup vs baseline: 4.5761x; 4.5761x over previous
#include <cuda_runtime.h>
#include <cuda_bf16.h>
#include <math.h>
#include <stdint.h>

// ============================================================================
// CTC decoder, round 3: mma.sync bf16 HMMA GEMM (tcgen05 unavailable: harness
// compiles at compute_103, no 'a' features) + smem-staged gather/scan.
//   K0 init     : out = LOGZERO, g_sumexp = 0
//   K1 convert  : x,W fp32 -> bf16
//   K2 gemm_mma : 128x128x32 CTA tile, m16n8k16 bf16, cp.async double buffer,
//                 fused exp-sum epilogue (atomicAdd per row)
//   K3 gather   : 31 fp32 dots per row, W rows staged in smem
//   K4 scan     : per-batch CTC recursion from smem
// ============================================================================

#define LOGZERO (-4290774016.0f)

__device__ float g_sumexp[32768];
__device__ float g_blank[32768];
__device__ float g_beam[32768 * 32];
__device__ __align__(16) __nv_bfloat16 g_xb[16384 * 512];
__device__ __align__(16) __nv_bfloat16 g_wb[4096 * 512];

// ---------------------------------------------------------------- helpers
__device__ __forceinline__ uint32_t smem_u32(const void* p) {
    uint32_t a;
    asm("{ .reg .u64 t; cvta.to.shared.u64 t, %1; cvt.u32.u64 %0, t; }"
        : "=r"(a) : "l"(p));
    return a;
}
#define CP_ASYNC16(dst, src) \
    asm volatile("cp.async.cg.shared.global [%0], [%1], 16;" :: "r"(dst), "l"(src))
#define CP_COMMIT() asm volatile("cp.async.commit_group;" ::: "memory")
#define CP_WAIT(n)  asm volatile("cp.async.wait_group %0;" :: "n"(n) : "memory")

__device__ __forceinline__ void ldmatrix_x4(uint32_t& r0, uint32_t& r1,
                                            uint32_t& r2, uint32_t& r3, uint32_t a) {
    asm volatile("ldmatrix.sync.aligned.m8n8.x4.shared.b16 {%0,%1,%2,%3}, [%4];"
                 : "=r"(r0), "=r"(r1), "=r"(r2), "=r"(r3) : "r"(a));
}
__device__ __forceinline__ void mma_bf16(float* c, const uint32_t* a, const uint32_t* b) {
    asm volatile(
        "mma.sync.aligned.m16n8k16.row.col.f32.bf16.bf16.f32 "
        "{%0,%1,%2,%3}, {%4,%5,%6,%7}, {%8,%9}, {%0,%1,%2,%3};"
        : "+f"(c[0]), "+f"(c[1]), "+f"(c[2]), "+f"(c[3])
        : "r"(a[0]), "r"(a[1]), "r"(a[2]), "r"(a[3]), "r"(b[0]), "r"(b[1]));
}

__device__ __forceinline__ float laexp(float a, float b) {
    float m = fmaxf(a, b);
    float d = fminf(a, b) - m;
    return m + __logf(1.0f + __expf(d));
}

// ---------------------------------------------------------------- K0: init
__global__ void init_kernel(float* __restrict__ out, int outN, int M) {
    int i = blockIdx.x * blockDim.x + threadIdx.x;
    if (i < outN) out[i] = LOGZERO;
    if (i < M)    g_sumexp[i] = 0.0f;
}

// ---------------------------------------------------------------- K1: convert
__global__ void convert_kernel(const float* __restrict__ x,
                               const float* __restrict__ W, int nx, int nw) {
    int i4 = (blockIdx.x * blockDim.x + threadIdx.x) << 2;
    if (i4 < nx) {
        float4 v = *reinterpret_cast<const float4*>(x + i4);
        *reinterpret_cast<__nv_bfloat162*>(g_xb + i4)     = __floats2bfloat162_rn(v.x, v.y);
        *reinterpret_cast<__nv_bfloat162*>(g_xb + i4 + 2) = __floats2bfloat162_rn(v.z, v.w);
    } else {
        int j4 = i4 - nx;
        if (j4 < nw) {
            float4 v = *reinterpret_cast<const float4*>(W + j4);
            *reinterpret_cast<__nv_bfloat162*>(g_wb + j4)     = __floats2bfloat162_rn(v.x, v.y);
            *reinterpret_cast<__nv_bfloat162*>(g_wb + j4 + 2) = __floats2bfloat162_rn(v.z, v.w);
        }
    }
}

// ---------------------------------------------------------------- K2: GEMM
// C[m,n] = sum_k X[m,k]*W[n,k] + bias[n]; g_sumexp[m] += sum_n exp(C[m,n]).
// 256 threads = 8 warps (4 m x 2 n), warp tile 32x64, BK=32, double buffer.
#define BM 128
#define BN 128
#define BK 32
#define LDS_STRIDE 40   // bf16 elements per smem row (80B: conflict-free ldmatrix)

__global__ __launch_bounds__(256, 2)
void gemm_mma_kernel(const float* __restrict__ bias, int M, int N, int K) {
    __shared__ __align__(16) __nv_bfloat16 sA[2][BM * LDS_STRIDE];
    __shared__ __align__(16) __nv_bfloat16 sB[2][BN * LDS_STRIDE];
    __shared__ float sbias[BN];

    const int tid  = threadIdx.x;
    const int lane = tid & 31;
    const int wid  = tid >> 5;
    const int wm   = wid & 3;        // 0..3  -> rows wm*32..+31
    const int wn   = wid >> 2;       // 0..1  -> cols wn*64..+63
    const int bm   = blockIdx.y << 7;
    const int bn   = blockIdx.x << 7;

    if (tid < BN) sbias[tid] = bias[bn + tid];

    // per-thread load coords: 512 uint4 per tile, 2 per thread per operand
    const int l_row0 = tid >> 2;             // 0..63
    const int l_c8   = (tid & 3) << 3;       // 0,8,16,24

    const __nv_bfloat16* gA = g_xb + (size_t)(bm + l_row0) * K + l_c8;
    const __nv_bfloat16* gB = g_wb + (size_t)(bn + l_row0) * K + l_c8;

    uint32_t sa_base = smem_u32(&sA[0][0]);
    uint32_t sb_base = smem_u32(&sB[0][0]);
    const uint32_t bufA = (uint32_t)(BM * LDS_STRIDE * 2);
    const uint32_t bufB = (uint32_t)(BN * LDS_STRIDE * 2);
    const uint32_t dstA0 = sa_base + (uint32_t)(l_row0 * LDS_STRIDE + l_c8) * 2;
    const uint32_t dstA1 = sa_base + (uint32_t)((l_row0 + 64) * LDS_STRIDE + l_c8) * 2;
    const uint32_t dstB0 = sb_base + (uint32_t)(l_row0 * LDS_STRIDE + l_c8) * 2;
    const uint32_t dstB1 = sb_base + (uint32_t)((l_row0 + 64) * LDS_STRIDE + l_c8) * 2;
    const size_t gstep64 = (size_t)64 * K;

    const int NC = K >> 5;           // 16

    // prologue: load chunk 0 into buf 0
    CP_ASYNC16(dstA0, gA);
    CP_ASYNC16(dstA1, gA + gstep64);
    CP_ASYNC16(dstB0, gB);
    CP_ASYNC16(dstB1, gB + gstep64);
    CP_COMMIT();

    float acc[2][8][4];
#pragma unroll
    for (int mt = 0; mt < 2; mt++)
#pragma unroll
        for (int nt = 0; nt < 8; nt++)
#pragma unroll
            for (int i = 0; i < 4; i++) acc[mt][nt][i] = 0.0f;

    // ldmatrix lane addressing (element offsets within a buffer)
    const int a_row = wm * 32 + (lane & 15);
    const int a_koff = (lane >> 4) << 3;
    const int b_row = wn * 64 + ((lane >> 4) << 3) + (lane & 7);
    const int b_koff = ((lane >> 3) & 1) << 3;

    for (int c = 0; c < NC; c++) {
        if (c + 1 < NC) {
            const __nv_bfloat16* gA1 = gA + (size_t)(c + 1) * BK;
            const __nv_bfloat16* gB1 = gB + (size_t)(c + 1) * BK;
            uint32_t off = ((c + 1) & 1) ? 1u : 0u;
            CP_ASYNC16(dstA0 + off * bufA, gA1);
            CP_ASYNC16(dstA1 + off * bufA, gA1 + gstep64);
            CP_ASYNC16(dstB0 + off * bufB, gB1);
            CP_ASYNC16(dstB1 + off * bufB, gB1 + gstep64);
            CP_COMMIT();
            CP_WAIT(1);
        } else {
            CP_WAIT(0);
        }
        __syncthreads();

        uint32_t abase = sa_base + ((c & 1) ? bufA : 0u);
        uint32_t bbase = sb_base + ((c & 1) ? bufB : 0u);

#pragma unroll
        for (int kt = 0; kt < 2; kt++) {
            uint32_t af[2][4];
#pragma unroll
            for (int mt = 0; mt < 2; mt++) {
                uint32_t addr = abase +
                    (uint32_t)((a_row + mt * 16) * LDS_STRIDE + kt * 16 + a_koff) * 2;
                ldmatrix_x4(af[mt][0], af[mt][1], af[mt][2], af[mt][3], addr);
            }
            uint32_t bf[8][2];
#pragma unroll
            for (int nt2 = 0; nt2 < 4; nt2++) {
                uint32_t addr = bbase +
                    (uint32_t)((b_row + nt2 * 16) * LDS_STRIDE + kt * 16 + b_koff) * 2;
                uint32_t r0, r1, r2, r3;
                ldmatrix_x4(r0, r1, r2, r3, addr);
                bf[nt2 * 2][0] = r0;  bf[nt2 * 2][1] = r1;
                bf[nt2 * 2 + 1][0] = r2;  bf[nt2 * 2 + 1][1] = r3;
            }
#pragma unroll
            for (int mt = 0; mt < 2; mt++)
#pragma unroll
                for (int nt = 0; nt < 8; nt++)
                    mma_bf16(acc[mt][nt], af[mt], bf[nt]);
        }
        __syncthreads();
    }

    // epilogue: exp-sum over n for each owned row, quad-reduce, atomicAdd
    const int gq = lane >> 2;            // groupID = row within 8
    const int qc = (lane & 3) << 1;      // col pair base
#pragma unroll
    for (int mt = 0; mt < 2; mt++) {
        float s0 = 0.0f, s1 = 0.0f;
#pragma unroll
        for (int nt = 0; nt < 8; nt++) {
            float b0 = sbias[wn * 64 + nt * 8 + qc];
            float b1 = sbias[wn * 64 + nt * 8 + qc + 1];
            s0 += __expf(acc[mt][nt][0] + b0) + __expf(acc[mt][nt][1] + b1);
            s1 += __expf(acc[mt][nt][2] + b0) + __expf(acc[mt][nt][3] + b1);
        }
        s0 += __shfl_xor_sync(0xffffffffu, s0, 1);
        s0 += __shfl_xor_sync(0xffffffffu, s0, 2);
        s1 += __shfl_xor_sync(0xffffffffu, s1, 1);
        s1 += __shfl_xor_sync(0xffffffffu, s1, 2);
        if ((lane & 3) == 0) {
            int r = bm + wm * 32 + mt * 16 + gq;
            atomicAdd(&g_sumexp[r], s0);
            atomicAdd(&g_sumexp[r + 8], s1);
        }
    }
}

// ---------------------------------------------------------------- K3: gather
__global__ void gather_kernel(const float* __restrict__ X, const float* __restrict__ Wm,
                              const float* __restrict__ bias,
                              const int* __restrict__ beam, const int* __restrict__ blankp,
                              int T, int D, int CB) {
    extern __shared__ float dsm[];
    const int b = blockIdx.x;
    const int ncols = CB + 1;
    float* sW    = dsm;
    float* sbias = dsm + ncols * D;
    int*   scol  = (int*)(sbias + ncols);

    const int tid  = threadIdx.x;
    const int lane = tid & 31;
    const int wrp  = tid >> 5;

    if (tid < ncols) {
        int col = (tid < CB) ? beam[b * CB + tid] : (blankp ? blankp[0] : 0);
        scol[tid]  = col;
        sbias[tid] = bias[col];
    }
    __syncthreads();
    for (int idx = tid; idx < ncols * D; idx += blockDim.x) {
        int r = idx / D, c = idx - r * D;
        sW[idx] = Wm[(size_t)scol[r] * D + c];
    }
    __syncthreads();

    const int nlanes = D >> 5;
    for (int tloc = wrp; tloc < 32; tloc += 8) {
        int t = (blockIdx.y << 5) + tloc;
        int row = b * T + t;
        float xr[16];
#pragma unroll
        for (int i = 0; i < 16; i++)
            xr[i] = (i < nlanes) ? X[(size_t)row * D + lane + (i << 5)] : 0.0f;
        for (int j = 0; j < ncols; j++) {
            float s = 0.0f;
            const float* wr = sW + j * D;
#pragma unroll
            for (int i = 0; i < 16; i++)
                if (i < nlanes) s += xr[i] * wr[lane + (i << 5)];
#pragma unroll
            for (int off = 16; off >= 1; off >>= 1)
                s += __shfl_xor_sync(0xffffffffu, s, off);
            if (lane == 0) {
                float val = s + sbias[j];
                if (j == CB) g_blank[row] = val;
                else         g_beam[(size_t)row * CB + j] = val;
            }
        }
    }
}

// ---------------------------------------------------------------- K4: scan
__global__ void scan_kernel(const int* __restrict__ xl, const int* __restrict__ beam,
                            const int* __restrict__ blankp, const int* __restrict__ eosp,
                            float* __restrict__ out, int T, int V, int CB, int Ly) {
    extern __shared__ float dsm[];
    float* s_lse = dsm;
    float* s_lpb = dsm + T;
    float* s_xn  = dsm + 2 * T;

    const int b = blockIdx.x;
    const int tid = threadIdx.x;
    const int blankv = blankp ? blankp[0] : 0;
    const int eosv   = eosp ? eosp[0] : (V - 1);
    const int xlb = xl[b];

    for (int t = tid; t < T; t += blockDim.x) {
        float lse = __logf(g_sumexp[b * T + t]);
        s_lse[t] = lse;
        s_lpb[t] = g_blank[b * T + t] - lse;
    }
    __syncthreads();
    for (int idx = tid; idx < T * CB; idx += blockDim.x) {
        int t = idx / CB, j = idx - t * CB;
        s_xn[t * 32 + j] = g_beam[(size_t)(b * T + t) * CB + j] - s_lse[t];
    }
    __syncthreads();

    if (tid < 32) {
        const int j = tid;
        const bool active = (j < CB);
        int start = Ly < (T - 1) ? Ly : (T - 1);
        int loop_start = start > 1 ? start : 1;

        float Pn = LOGZERO, Pb = LOGZERO, acc = LOGZERO;
        float cum = 0.0f, pref = 0.0f, eosval = 0.0f;

        for (int t = 0; t < T; t++) {
            float lpb = s_lpb[t];
            cum = (t == 0) ? lpb : (cum + lpb);
            if (active) {
                float xn = s_xn[t * 32 + j];
                if (t == 0 && start == 0) {
                    Pn = xn; Pb = LOGZERO;
                } else if (t >= loop_start) {
                    float pn = laexp(Pn, pref) + xn;
                    float pb = laexp(Pn, Pb) + lpb;
                    Pn = pn; Pb = pb;
                }
                if (t >= start && t < xlb)
                    acc = laexp(acc, laexp(Pn, Pb));
            }
            if (t == xlb - 1) eosval = cum;
            pref = cum;
        }

        if (active) out[(size_t)b * V + beam[b * CB + j]] = acc;
        __syncwarp();
        if (j == 0) {
            out[(size_t)b * V + eosv]   = (xlb >= 1 && xlb <= T) ? eosval : 0.0f;
            out[(size_t)b * V + blankv] = LOGZERO;
        }
    }
}

// ---------------------------------------------------------------------------
extern "C" void kernel_launch(void* const* d_in, const int* in_sizes, int n_in,
                              void* d_out, int out_size) {
    const float* x    = (const float*)d_in[0];   // (B,T,D)
    const float* W    = (const float*)d_in[1];   // (V,D)
    const float* bias = (const float*)d_in[2];   // (V,)
    const int*   xl   = (const int*)d_in[3];     // (B,)
    // d_in[4] = y : unused (lastPsum == lastP1 in f32, branch collapses)
    const int*   beam = (const int*)d_in[5];     // (B,CB)
    const int*   blankp = (n_in > 6) ? (const int*)d_in[6] : nullptr;
    const int*   eosp   = (n_in > 7) ? (const int*)d_in[7] : nullptr;

    const int B  = in_sizes[3];
    const int V  = in_sizes[2];
    const int D  = in_sizes[1] / V;
    const int T  = in_sizes[0] / (B * D);
    const int CB = in_sizes[5] / B;
    const int Ly = in_sizes[4] / B;
    const int M  = B * T;

    float* out = (float*)d_out;

    int initN = out_size > M ? out_size : M;
    init_kernel<<<(initN + 255) / 256, 256>>>(out, out_size, M);

    const int nx = M * D, nw = V * D;
    int tot4 = (nx + nw) >> 2;
    convert_kernel<<<(tot4 + 255) / 256, 256>>>(x, W, nx, nw);

    dim3 gg(V >> 7, M >> 7);
    gemm_mma_kernel<<<gg, 256>>>(bias, M, V, D);

    int gsm = ((CB + 1) * D + 2 * (CB + 1)) * 4;
    cudaFuncSetAttribute(gather_kernel,
                         cudaFuncAttributeMaxDynamicSharedMemorySize, gsm);
    dim3 gth(B, T >> 5);
    gather_kernel<<<gth, 256, gsm>>>(x, W, bias, beam, blankp, T, D, CB);

    int ssm = (2 * T + T * 32) * 4;
    cudaFuncSetAttribute(scan_kernel,
                         cudaFuncAttributeMaxDynamicSharedMemorySize, ssm);
    scan_kernel<<<B, 256, ssm>>>(xl, beam, blankp, eosp, out, T, V, CB, Ly);
}

// round 4
// speedup vs baseline: 5.6305x; 1.2304x over previous
#include <cuda_runtime.h>
#include <cuda_bf16.h>
#include <math.h>
#include <stdint.h>

// ============================================================================
// CTC decoder, round 4: gather folded into GEMM epilogue via colmap scatter.
//   K0 init     : out = LOGZERO, g_sumexp = 0, g_colmap = -1
//   K1 colmap   : scatter beam/blank column -> slot per batch
//   K2 convert  : x,W fp32 -> bf16
//   K3 gemm_mma : 128x128x32 bf16 m16n8k16, cp.async double buffer,
//                 fused exp-sum epilogue + beam/blank extraction
//   K4 scan     : per-batch CTC recursion from smem
// ============================================================================

#define LOGZERO (-4290774016.0f)

__device__ float g_sumexp[32768];
__device__ float g_blank[32768];
__device__ float g_beam[32768 * 32];
__device__ int   g_colmap[32 * 4096];          // B*V, slot or -1
__device__ __align__(16) __nv_bfloat16 g_xb[16384 * 512];
__device__ __align__(16) __nv_bfloat16 g_wb[4096 * 512];

// ---------------------------------------------------------------- helpers
__device__ __forceinline__ uint32_t smem_u32(const void* p) {
    uint32_t a;
    asm("{ .reg .u64 t; cvta.to.shared.u64 t, %1; cvt.u32.u64 %0, t; }"
        : "=r"(a) : "l"(p));
    return a;
}
#define CP_ASYNC16(dst, src) \
    asm volatile("cp.async.cg.shared.global [%0], [%1], 16;" :: "r"(dst), "l"(src))
#define CP_COMMIT() asm volatile("cp.async.commit_group;" ::: "memory")
#define CP_WAIT(n)  asm volatile("cp.async.wait_group %0;" :: "n"(n) : "memory")

__device__ __forceinline__ void ldmatrix_x4(uint32_t& r0, uint32_t& r1,
                                            uint32_t& r2, uint32_t& r3, uint32_t a) {
    asm volatile("ldmatrix.sync.aligned.m8n8.x4.shared.b16 {%0,%1,%2,%3}, [%4];"
                 : "=r"(r0), "=r"(r1), "=r"(r2), "=r"(r3) : "r"(a));
}
__device__ __forceinline__ void mma_bf16(float* c, const uint32_t* a, const uint32_t* b) {
    asm volatile(
        "mma.sync.aligned.m16n8k16.row.col.f32.bf16.bf16.f32 "
        "{%0,%1,%2,%3}, {%4,%5,%6,%7}, {%8,%9}, {%0,%1,%2,%3};"
        : "+f"(c[0]), "+f"(c[1]), "+f"(c[2]), "+f"(c[3])
        : "r"(a[0]), "r"(a[1]), "r"(a[2]), "r"(a[3]), "r"(b[0]), "r"(b[1]));
}

__device__ __forceinline__ float laexp(float a, float b) {
    float m = fmaxf(a, b);
    float d = fminf(a, b) - m;
    return m + __logf(1.0f + __expf(d));
}

// ---------------------------------------------------------------- K0: init
__global__ void init_kernel(float* __restrict__ out, int outN, int M) {
    int i = blockIdx.x * blockDim.x + threadIdx.x;
    if (i < outN) { out[i] = LOGZERO; g_colmap[i] = -1; }
    if (i < M)    g_sumexp[i] = 0.0f;
}

// ---------------------------------------------------------------- K1: colmap
__global__ void colmap_kernel(const int* __restrict__ beam,
                              const int* __restrict__ blankp,
                              int B, int V, int CB) {
    int i = blockIdx.x * blockDim.x + threadIdx.x;      // b*(CB+1)+j
    int ncols = CB + 1;
    if (i >= B * ncols) return;
    int b = i / ncols, j = i - b * ncols;
    int col = (j < CB) ? beam[b * CB + j] : (blankp ? blankp[0] : 0);
    g_colmap[b * V + col] = j;                          // j==CB means blank
}

// ---------------------------------------------------------------- K2: convert
__global__ void convert_kernel(const float* __restrict__ x,
                               const float* __restrict__ W, int nx, int nw) {
    int i4 = (blockIdx.x * blockDim.x + threadIdx.x) << 2;
    if (i4 < nx) {
        float4 v = *reinterpret_cast<const float4*>(x + i4);
        *reinterpret_cast<__nv_bfloat162*>(g_xb + i4)     = __floats2bfloat162_rn(v.x, v.y);
        *reinterpret_cast<__nv_bfloat162*>(g_xb + i4 + 2) = __floats2bfloat162_rn(v.z, v.w);
    } else {
        int j4 = i4 - nx;
        if (j4 < nw) {
            float4 v = *reinterpret_cast<const float4*>(W + j4);
            *reinterpret_cast<__nv_bfloat162*>(g_wb + j4)     = __floats2bfloat162_rn(v.x, v.y);
            *reinterpret_cast<__nv_bfloat162*>(g_wb + j4 + 2) = __floats2bfloat162_rn(v.z, v.w);
        }
    }
}

// ---------------------------------------------------------------- K3: GEMM
// C[m,n] = sum_k X[m,k]*W[n,k] + bias[n]; g_sumexp[m] += sum_n exp(C[m,n]);
// beam/blank logits scattered via colmap.  8 warps (4m x 2n), warp 32x64.
#define BM 128
#define BN 128
#define BK 32
#define LDS_STRIDE 40

__global__ __launch_bounds__(256, 2)
void gemm_mma_kernel(const float* __restrict__ bias, int M, int N, int K,
                     int T, int CB) {
    __shared__ __align__(16) __nv_bfloat16 sA[2][BM * LDS_STRIDE];
    __shared__ __align__(16) __nv_bfloat16 sB[2][BN * LDS_STRIDE];
    __shared__ float sbias[BN];
    __shared__ int   sslot[BN];

    const int tid  = threadIdx.x;
    const int lane = tid & 31;
    const int wid  = tid >> 5;
    const int wm   = wid & 3;
    const int wn   = wid >> 2;
    const int bm   = blockIdx.y << 7;
    const int bn   = blockIdx.x << 7;
    const int bcta = bm / T;                 // batch of this row-block (128 | T)

    if (tid < BN) {
        sbias[tid] = bias[bn + tid];
        sslot[tid] = g_colmap[bcta * N + bn + tid];
    }

    const int l_row0 = tid >> 2;
    const int l_c8   = (tid & 3) << 3;

    const __nv_bfloat16* gA = g_xb + (size_t)(bm + l_row0) * K + l_c8;
    const __nv_bfloat16* gB = g_wb + (size_t)(bn + l_row0) * K + l_c8;

    uint32_t sa_base = smem_u32(&sA[0][0]);
    uint32_t sb_base = smem_u32(&sB[0][0]);
    const uint32_t bufA = (uint32_t)(BM * LDS_STRIDE * 2);
    const uint32_t bufB = (uint32_t)(BN * LDS_STRIDE * 2);
    const uint32_t dstA0 = sa_base + (uint32_t)(l_row0 * LDS_STRIDE + l_c8) * 2;
    const uint32_t dstA1 = sa_base + (uint32_t)((l_row0 + 64) * LDS_STRIDE + l_c8) * 2;
    const uint32_t dstB0 = sb_base + (uint32_t)(l_row0 * LDS_STRIDE + l_c8) * 2;
    const uint32_t dstB1 = sb_base + (uint32_t)((l_row0 + 64) * LDS_STRIDE + l_c8) * 2;
    const size_t gstep64 = (size_t)64 * K;

    const int NC = K >> 5;

    CP_ASYNC16(dstA0, gA);
    CP_ASYNC16(dstA1, gA + gstep64);
    CP_ASYNC16(dstB0, gB);
    CP_ASYNC16(dstB1, gB + gstep64);
    CP_COMMIT();

    float acc[2][8][4];
#pragma unroll
    for (int mt = 0; mt < 2; mt++)
#pragma unroll
        for (int nt = 0; nt < 8; nt++)
#pragma unroll
            for (int i = 0; i < 4; i++) acc[mt][nt][i] = 0.0f;

    const int a_row = wm * 32 + (lane & 15);
    const int a_koff = (lane >> 4) << 3;
    const int b_row = wn * 64 + ((lane >> 4) << 3) + (lane & 7);
    const int b_koff = ((lane >> 3) & 1) << 3;

    for (int c = 0; c < NC; c++) {
        if (c + 1 < NC) {
            const __nv_bfloat16* gA1 = gA + (size_t)(c + 1) * BK;
            const __nv_bfloat16* gB1 = gB + (size_t)(c + 1) * BK;
            uint32_t off = ((c + 1) & 1) ? 1u : 0u;
            CP_ASYNC16(dstA0 + off * bufA, gA1);
            CP_ASYNC16(dstA1 + off * bufA, gA1 + gstep64);
            CP_ASYNC16(dstB0 + off * bufB, gB1);
            CP_ASYNC16(dstB1 + off * bufB, gB1 + gstep64);
            CP_COMMIT();
            CP_WAIT(1);
        } else {
            CP_WAIT(0);
        }
        __syncthreads();

        uint32_t abase = sa_base + ((c & 1) ? bufA : 0u);
        uint32_t bbase = sb_base + ((c & 1) ? bufB : 0u);

#pragma unroll
        for (int kt = 0; kt < 2; kt++) {
            uint32_t af[2][4];
#pragma unroll
            for (int mt = 0; mt < 2; mt++) {
                uint32_t addr = abase +
                    (uint32_t)((a_row + mt * 16) * LDS_STRIDE + kt * 16 + a_koff) * 2;
                ldmatrix_x4(af[mt][0], af[mt][1], af[mt][2], af[mt][3], addr);
            }
            uint32_t bf[8][2];
#pragma unroll
            for (int nt2 = 0; nt2 < 4; nt2++) {
                uint32_t addr = bbase +
                    (uint32_t)((b_row + nt2 * 16) * LDS_STRIDE + kt * 16 + b_koff) * 2;
                uint32_t r0, r1, r2, r3;
                ldmatrix_x4(r0, r1, r2, r3, addr);
                bf[nt2 * 2][0] = r0;  bf[nt2 * 2][1] = r1;
                bf[nt2 * 2 + 1][0] = r2;  bf[nt2 * 2 + 1][1] = r3;
            }
#pragma unroll
            for (int mt = 0; mt < 2; mt++)
#pragma unroll
                for (int nt = 0; nt < 8; nt++)
                    mma_bf16(acc[mt][nt], af[mt], bf[nt]);
        }
        __syncthreads();
    }

    // epilogue: exp-sum + colmap scatter of beam/blank logits
    const int gq = lane >> 2;
    const int qc = (lane & 3) << 1;
#pragma unroll
    for (int mt = 0; mt < 2; mt++) {
        const int r0 = bm + wm * 32 + mt * 16 + gq;
        float s0 = 0.0f, s1 = 0.0f;
#pragma unroll
        for (int nt = 0; nt < 8; nt++) {
            const int c0 = wn * 64 + nt * 8 + qc;
            float b0 = sbias[c0];
            float b1 = sbias[c0 + 1];
            float v00 = acc[mt][nt][0] + b0;   // (r0,   c0)
            float v01 = acc[mt][nt][1] + b1;   // (r0,   c0+1)
            float v10 = acc[mt][nt][2] + b0;   // (r0+8, c0)
            float v11 = acc[mt][nt][3] + b1;   // (r0+8, c0+1)
            s0 += __expf(v00) + __expf(v01);
            s1 += __expf(v10) + __expf(v11);
            int sl0 = sslot[c0], sl1 = sslot[c0 + 1];
            if (sl0 >= 0) {
                if (sl0 == CB) { g_blank[r0] = v00; g_blank[r0 + 8] = v10; }
                else { g_beam[(size_t)r0 * CB + sl0] = v00;
                       g_beam[(size_t)(r0 + 8) * CB + sl0] = v10; }
            }
            if (sl1 >= 0) {
                if (sl1 == CB) { g_blank[r0] = v01; g_blank[r0 + 8] = v11; }
                else { g_beam[(size_t)r0 * CB + sl1] = v01;
                       g_beam[(size_t)(r0 + 8) * CB + sl1] = v11; }
            }
        }
        s0 += __shfl_xor_sync(0xffffffffu, s0, 1);
        s0 += __shfl_xor_sync(0xffffffffu, s0, 2);
        s1 += __shfl_xor_sync(0xffffffffu, s1, 1);
        s1 += __shfl_xor_sync(0xffffffffu, s1, 2);
        if ((lane & 3) == 0) {
            atomicAdd(&g_sumexp[r0], s0);
            atomicAdd(&g_sumexp[r0 + 8], s1);
        }
    }
}

// ---------------------------------------------------------------- K4: scan
__global__ void scan_kernel(const int* __restrict__ xl, const int* __restrict__ beam,
                            const int* __restrict__ blankp, const int* __restrict__ eosp,
                            float* __restrict__ out, int T, int V, int CB, int Ly) {
    extern __shared__ float dsm[];
    float* s_lse = dsm;
    float* s_lpb = dsm + T;
    float* s_xn  = dsm + 2 * T;

    const int b = blockIdx.x;
    const int tid = threadIdx.x;
    const int blankv = blankp ? blankp[0] : 0;
    const int eosv   = eosp ? eosp[0] : (V - 1);
    const int xlb = xl[b];

    for (int t = tid; t < T; t += blockDim.x) {
        float lse = __logf(g_sumexp[b * T + t]);
        s_lse[t] = lse;
        s_lpb[t] = g_blank[b * T + t] - lse;
    }
    __syncthreads();
    for (int idx = tid; idx < T * CB; idx += blockDim.x) {
        int t = idx / CB, j = idx - t * CB;
        s_xn[t * 32 + j] = g_beam[(size_t)(b * T + t) * CB + j] - s_lse[t];
    }
    __syncthreads();

    if (tid < 32) {
        const int j = tid;
        const bool active = (j < CB);
        int start = Ly < (T - 1) ? Ly : (T - 1);
        int loop_start = start > 1 ? start : 1;

        float Pn = LOGZERO, Pb = LOGZERO, acc = LOGZERO;
        float cum = 0.0f, pref = 0.0f, eosval = 0.0f;

        for (int t = 0; t < T; t++) {
            float lpb = s_lpb[t];
            cum = (t == 0) ? lpb : (cum + lpb);
            if (active) {
                float xn = s_xn[t * 32 + j];
                if (t == 0 && start == 0) {
                    Pn = xn; Pb = LOGZERO;
                } else if (t >= loop_start) {
                    float pn = laexp(Pn, pref) + xn;
                    float pb = laexp(Pn, Pb) + lpb;
                    Pn = pn; Pb = pb;
                }
                if (t >= start && t < xlb)
                    acc = laexp(acc, laexp(Pn, Pb));
            }
            if (t == xlb - 1) eosval = cum;
            pref = cum;
        }

        if (active) out[(size_t)b * V + beam[b * CB + j]] = acc;
        __syncwarp();
        if (j == 0) {
            out[(size_t)b * V + eosv]   = (xlb >= 1 && xlb <= T) ? eosval : 0.0f;
            out[(size_t)b * V + blankv] = LOGZERO;
        }
    }
}

// ---------------------------------------------------------------------------
extern "C" void kernel_launch(void* const* d_in, const int* in_sizes, int n_in,
                              void* d_out, int out_size) {
    const float* x    = (const float*)d_in[0];   // (B,T,D)
    const float* W    = (const float*)d_in[1];   // (V,D)
    const float* bias = (const float*)d_in[2];   // (V,)
    const int*   xl   = (const int*)d_in[3];     // (B,)
    // d_in[4] = y : unused (lastPsum == lastP1 in f32, branch collapses)
    const int*   beam = (const int*)d_in[5];     // (B,CB)
    const int*   blankp = (n_in > 6) ? (const int*)d_in[6] : nullptr;
    const int*   eosp   = (n_in > 7) ? (const int*)d_in[7] : nullptr;

    const int B  = in_sizes[3];
    const int V  = in_sizes[2];
    const int D  = in_sizes[1] / V;
    const int T  = in_sizes[0] / (B * D);
    const int CB = in_sizes[5] / B;
    const int Ly = in_sizes[4] / B;
    const int M  = B * T;

    float* out = (float*)d_out;

    int initN = out_size > M ? out_size : M;    // out_size == B*V == colmap size
    init_kernel<<<(initN + 255) / 256, 256>>>(out, out_size, M);

    int nmap = B * (CB + 1);
    colmap_kernel<<<(nmap + 127) / 128, 128>>>(beam, blankp, B, V, CB);

    const int nx = M * D, nw = V * D;
    int tot4 = (nx + nw) >> 2;
    convert_kernel<<<(tot4 + 255) / 256, 256>>>(x, W, nx, nw);

    dim3 gg(V >> 7, M >> 7);
    gemm_mma_kernel<<<gg, 256>>>(bias, M, V, D, T, CB);

    int ssm = (2 * T + T * 32) * 4;
    cudaFuncSetAttribute(scan_kernel,
                         cudaFuncAttributeMaxDynamicSharedMemorySize, ssm);
    scan_kernel<<<B, 256, ssm>>>(xl, beam, blankp, eosp, out, T, V, CB, Ly);
}

// round 5
// speedup vs baseline: 6.1934x; 1.1000x over previous
#include <cuda_runtime.h>
#include <cuda_bf16.h>
#include <math.h>
#include <stdint.h>

// ============================================================================
// CTC decoder, round 5: 3 launches total.
//   K1 prep     : out=LOGZERO, g_sumexp=0, x/W fp32->bf16
//   K2 gemm_mma : 128x128x64 bf16 m16n8k16, cp.async double buffer,
//                 in-CTA beam-slot map, fused exp-sum + beam/blank extraction
//   K3 scan     : per-batch CTC recursion from smem
// ============================================================================

#define LOGZERO (-4290774016.0f)

__device__ float g_sumexp[32768];
__device__ float g_blank[32768];
__device__ float g_beam[32768 * 32];
__device__ __align__(16) __nv_bfloat16 g_xb[16384 * 512];
__device__ __align__(16) __nv_bfloat16 g_wb[4096 * 512];

// ---------------------------------------------------------------- helpers
__device__ __forceinline__ uint32_t smem_u32(const void* p) {
    uint32_t a;
    asm("{ .reg .u64 t; cvta.to.shared.u64 t, %1; cvt.u32.u64 %0, t; }"
        : "=r"(a) : "l"(p));
    return a;
}
#define CP_ASYNC16(dst, src) \
    asm volatile("cp.async.cg.shared.global [%0], [%1], 16;" :: "r"(dst), "l"(src))
#define CP_COMMIT() asm volatile("cp.async.commit_group;" ::: "memory")
#define CP_WAIT(n)  asm volatile("cp.async.wait_group %0;" :: "n"(n) : "memory")

__device__ __forceinline__ void ldmatrix_x4(uint32_t& r0, uint32_t& r1,
                                            uint32_t& r2, uint32_t& r3, uint32_t a) {
    asm volatile("ldmatrix.sync.aligned.m8n8.x4.shared.b16 {%0,%1,%2,%3}, [%4];"
                 : "=r"(r0), "=r"(r1), "=r"(r2), "=r"(r3) : "r"(a));
}
__device__ __forceinline__ void mma_bf16(float* c, const uint32_t* a, const uint32_t* b) {
    asm volatile(
        "mma.sync.aligned.m16n8k16.row.col.f32.bf16.bf16.f32 "
        "{%0,%1,%2,%3}, {%4,%5,%6,%7}, {%8,%9}, {%0,%1,%2,%3};"
        : "+f"(c[0]), "+f"(c[1]), "+f"(c[2]), "+f"(c[3])
        : "r"(a[0]), "r"(a[1]), "r"(a[2]), "r"(a[3]), "r"(b[0]), "r"(b[1]));
}

__device__ __forceinline__ float laexp(float a, float b) {
    float m = fmaxf(a, b);
    float d = fminf(a, b) - m;
    return m + __logf(1.0f + __expf(d));
}

// ---------------------------------------------------------------- K1: prep
__global__ void prep_kernel(const float* __restrict__ x, const float* __restrict__ W,
                            float* __restrict__ out, int nx, int nw, int outN, int M) {
    int idx = blockIdx.x * blockDim.x + threadIdx.x;
    if (idx < outN) out[idx] = LOGZERO;
    if (idx < M)    g_sumexp[idx] = 0.0f;
    int i4 = idx << 2;
    if (i4 < nx) {
        float4 v = *reinterpret_cast<const float4*>(x + i4);
        *reinterpret_cast<__nv_bfloat162*>(g_xb + i4)     = __floats2bfloat162_rn(v.x, v.y);
        *reinterpret_cast<__nv_bfloat162*>(g_xb + i4 + 2) = __floats2bfloat162_rn(v.z, v.w);
    } else {
        int j4 = i4 - nx;
        if (j4 < nw) {
            float4 v = *reinterpret_cast<const float4*>(W + j4);
            *reinterpret_cast<__nv_bfloat162*>(g_wb + j4)     = __floats2bfloat162_rn(v.x, v.y);
            *reinterpret_cast<__nv_bfloat162*>(g_wb + j4 + 2) = __floats2bfloat162_rn(v.z, v.w);
        }
    }
}

// ---------------------------------------------------------------- K2: GEMM
// C[m,n] = sum_k X[m,k]*W[n,k] + bias[n]; g_sumexp[m] += sum_n exp(C[m,n]);
// beam/blank logits scattered via in-CTA slot map.
// 8 warps (4m x 2n), warp tile 32x64, BK=64, double buffer (dynamic smem).
#define BM 128
#define BN 128
#define BK 64
#define STRIDE 72                       // bf16 elems/row: 144B, conflict-free
#define BUFB (BM * STRIDE * 2)          // 18432 B per operand-buffer
#define SM_BIAS (4 * BUFB)              // after 2xA + 2xB buffers
#define SM_SLOT (SM_BIAS + 512)
#define SM_TOTAL (SM_SLOT + 512)

__global__ __launch_bounds__(256, 2)
void gemm_mma_kernel(const float* __restrict__ bias,
                     const int* __restrict__ beam, const int* __restrict__ blankp,
                     int M, int N, int K, int T, int CB) {
    extern __shared__ __align__(16) char smem[];
    float* sbias = reinterpret_cast<float*>(smem + SM_BIAS);
    int*   sslot = reinterpret_cast<int*>(smem + SM_SLOT);

    const int tid  = threadIdx.x;
    const int lane = tid & 31;
    const int wid  = tid >> 5;
    const int wm   = wid & 3;
    const int wn   = wid >> 2;
    const int bm   = blockIdx.y << 7;
    const int bn   = blockIdx.x << 7;
    const int bcta = bm / T;

    if (tid < BN) {
        sbias[tid] = bias[bn + tid];
        sslot[tid] = -1;
    }
    __syncthreads();
    if (tid <= CB) {
        int col = (tid < CB) ? beam[bcta * CB + tid] : (blankp ? blankp[0] : 0);
        if ((unsigned)(col - bn) < (unsigned)BN) sslot[col - bn] = tid;  // CB = blank
    }

    // cp.async coords: 128 rows x 8 uint4 per operand, 4 passes of 32 rows
    const int l_row = tid >> 3;             // 0..31
    const int l_c8  = (tid & 7) << 3;
    const __nv_bfloat16* gA = g_xb + (size_t)(bm + l_row) * K + l_c8;
    const __nv_bfloat16* gB = g_wb + (size_t)(bn + l_row) * K + l_c8;

    const uint32_t sa_u32 = smem_u32(smem);
    const uint32_t sb_u32 = sa_u32 + 2 * BUFB;
    const uint32_t dA = sa_u32 + (uint32_t)(l_row * STRIDE + l_c8) * 2;
    const uint32_t dB = sb_u32 + (uint32_t)(l_row * STRIDE + l_c8) * 2;
    const size_t gp = (size_t)32 * K;       // 32-row step
    const uint32_t sp = 32 * STRIDE * 2;    // 4608 B

    const int NC = K >> 6;                  // chunks of 64

    // prologue: chunk 0 -> buf 0
#pragma unroll
    for (int p = 0; p < 4; p++) {
        CP_ASYNC16(dA + p * sp, gA + p * gp);
        CP_ASYNC16(dB + p * sp, gB + p * gp);
    }
    CP_COMMIT();

    float acc[2][8][4];
#pragma unroll
    for (int mt = 0; mt < 2; mt++)
#pragma unroll
        for (int nt = 0; nt < 8; nt++)
#pragma unroll
            for (int i = 0; i < 4; i++) acc[mt][nt][i] = 0.0f;

    const int a_row  = wm * 32 + (lane & 15);
    const int a_koff = (lane >> 4) << 3;
    const int b_row  = wn * 64 + ((lane >> 4) << 3) + (lane & 7);
    const int b_koff = ((lane >> 3) & 1) << 3;

    for (int c = 0; c < NC; c++) {
        if (c + 1 < NC) {
            uint32_t o = ((c + 1) & 1) * BUFB;
            const __nv_bfloat16* gA1 = gA + (size_t)(c + 1) * BK;
            const __nv_bfloat16* gB1 = gB + (size_t)(c + 1) * BK;
#pragma unroll
            for (int p = 0; p < 4; p++) {
                CP_ASYNC16(dA + o + p * sp, gA1 + p * gp);
                CP_ASYNC16(dB + o + p * sp, gB1 + p * gp);
            }
            CP_COMMIT();
            CP_WAIT(1);
        } else {
            CP_WAIT(0);
        }
        __syncthreads();

        const uint32_t abase = sa_u32 + (c & 1) * BUFB;
        const uint32_t bbase = sb_u32 + (c & 1) * BUFB;

#pragma unroll
        for (int kt = 0; kt < 4; kt++) {
            uint32_t af[2][4];
#pragma unroll
            for (int mt = 0; mt < 2; mt++) {
                uint32_t addr = abase +
                    (uint32_t)((a_row + mt * 16) * STRIDE + kt * 16 + a_koff) * 2;
                ldmatrix_x4(af[mt][0], af[mt][1], af[mt][2], af[mt][3], addr);
            }
            uint32_t bf[8][2];
#pragma unroll
            for (int nt2 = 0; nt2 < 4; nt2++) {
                uint32_t addr = bbase +
                    (uint32_t)((b_row + nt2 * 16) * STRIDE + kt * 16 + b_koff) * 2;
                uint32_t r0, r1, r2, r3;
                ldmatrix_x4(r0, r1, r2, r3, addr);
                bf[nt2 * 2][0] = r0;      bf[nt2 * 2][1] = r1;
                bf[nt2 * 2 + 1][0] = r2;  bf[nt2 * 2 + 1][1] = r3;
            }
#pragma unroll
            for (int mt = 0; mt < 2; mt++)
#pragma unroll
                for (int nt = 0; nt < 8; nt++)
                    mma_bf16(acc[mt][nt], af[mt], bf[nt]);
        }
        __syncthreads();
    }

    // epilogue: exp-sum + slot scatter of beam/blank logits
    const int gq = lane >> 2;
    const int qc = (lane & 3) << 1;
#pragma unroll
    for (int mt = 0; mt < 2; mt++) {
        const int r0 = bm + wm * 32 + mt * 16 + gq;
        float s0 = 0.0f, s1 = 0.0f;
#pragma unroll
        for (int nt = 0; nt < 8; nt++) {
            const int c0 = wn * 64 + nt * 8 + qc;
            float b0 = sbias[c0];
            float b1 = sbias[c0 + 1];
            float v00 = acc[mt][nt][0] + b0;
            float v01 = acc[mt][nt][1] + b1;
            float v10 = acc[mt][nt][2] + b0;
            float v11 = acc[mt][nt][3] + b1;
            s0 += __expf(v00) + __expf(v01);
            s1 += __expf(v10) + __expf(v11);
            int sl0 = sslot[c0], sl1 = sslot[c0 + 1];
            if (sl0 >= 0) {
                if (sl0 == CB) { g_blank[r0] = v00; g_blank[r0 + 8] = v10; }
                else { g_beam[(size_t)r0 * CB + sl0] = v00;
                       g_beam[(size_t)(r0 + 8) * CB + sl0] = v10; }
            }
            if (sl1 >= 0) {
                if (sl1 == CB) { g_blank[r0] = v01; g_blank[r0 + 8] = v11; }
                else { g_beam[(size_t)r0 * CB + sl1] = v01;
                       g_beam[(size_t)(r0 + 8) * CB + sl1] = v11; }
            }
        }
        s0 += __shfl_xor_sync(0xffffffffu, s0, 1);
        s0 += __shfl_xor_sync(0xffffffffu, s0, 2);
        s1 += __shfl_xor_sync(0xffffffffu, s1, 1);
        s1 += __shfl_xor_sync(0xffffffffu, s1, 2);
        if ((lane & 3) == 0) {
            atomicAdd(&g_sumexp[r0], s0);
            atomicAdd(&g_sumexp[r0 + 8], s1);
        }
    }
}

// ---------------------------------------------------------------- K3: scan
__global__ void scan_kernel(const int* __restrict__ xl, const int* __restrict__ beam,
                            const int* __restrict__ blankp, const int* __restrict__ eosp,
                            float* __restrict__ out, int T, int V, int CB, int Ly) {
    extern __shared__ float dsm[];
    float* s_lse = dsm;
    float* s_lpb = dsm + T;
    float* s_xn  = dsm + 2 * T;

    const int b = blockIdx.x;
    const int tid = threadIdx.x;
    const int blankv = blankp ? blankp[0] : 0;
    const int eosv   = eosp ? eosp[0] : (V - 1);
    const int xlb = xl[b];

    for (int t = tid; t < T; t += blockDim.x) {
        float lse = __logf(g_sumexp[b * T + t]);
        s_lse[t] = lse;
        s_lpb[t] = g_blank[b * T + t] - lse;
    }
    __syncthreads();
    for (int idx = tid; idx < T * CB; idx += blockDim.x) {
        int t = idx / CB, j = idx - t * CB;
        s_xn[t * 32 + j] = g_beam[(size_t)(b * T + t) * CB + j] - s_lse[t];
    }
    __syncthreads();

    if (tid < 32) {
        const int j = tid;
        const bool active = (j < CB);
        int start = Ly < (T - 1) ? Ly : (T - 1);
        int loop_start = start > 1 ? start : 1;

        float Pn = LOGZERO, Pb = LOGZERO, acc = LOGZERO;
        float cum = 0.0f, pref = 0.0f, eosval = 0.0f;

        for (int t = 0; t < T; t++) {
            float lpb = s_lpb[t];
            cum = (t == 0) ? lpb : (cum + lpb);
            if (active) {
                float xn = s_xn[t * 32 + j];
                if (t == 0 && start == 0) {
                    Pn = xn; Pb = LOGZERO;
                } else if (t >= loop_start) {
                    float pn = laexp(Pn, pref) + xn;
                    float pb = laexp(Pn, Pb) + lpb;
                    Pn = pn; Pb = pb;
                }
                if (t >= start && t < xlb)
                    acc = laexp(acc, laexp(Pn, Pb));
            }
            if (t == xlb - 1) eosval = cum;
            pref = cum;
        }

        if (active) out[(size_t)b * V + beam[b * CB + j]] = acc;
        __syncwarp();
        if (j == 0) {
            out[(size_t)b * V + eosv]   = (xlb >= 1 && xlb <= T) ? eosval : 0.0f;
            out[(size_t)b * V + blankv] = LOGZERO;
        }
    }
}

// ---------------------------------------------------------------------------
extern "C" void kernel_launch(void* const* d_in, const int* in_sizes, int n_in,
                              void* d_out, int out_size) {
    const float* x    = (const float*)d_in[0];   // (B,T,D)
    const float* W    = (const float*)d_in[1];   // (V,D)
    const float* bias = (const float*)d_in[2];   // (V,)
    const int*   xl   = (const int*)d_in[3];     // (B,)
    // d_in[4] = y : unused (lastPsum == lastP1 in f32, branch collapses)
    const int*   beam = (const int*)d_in[5];     // (B,CB)
    const int*   blankp = (n_in > 6) ? (const int*)d_in[6] : nullptr;
    const int*   eosp   = (n_in > 7) ? (const int*)d_in[7] : nullptr;

    const int B  = in_sizes[3];
    const int V  = in_sizes[2];
    const int D  = in_sizes[1] / V;
    const int T  = in_sizes[0] / (B * D);
    const int CB = in_sizes[5] / B;
    const int Ly = in_sizes[4] / B;
    const int M  = B * T;

    float* out = (float*)d_out;

    const int nx = M * D, nw = V * D;
    int nthr = (nx + nw) >> 2;
    if (nthr < out_size) nthr = out_size;
    prep_kernel<<<(nthr + 255) / 256, 256>>>(x, W, out, nx, nw, out_size, M);

    cudaFuncSetAttribute(gemm_mma_kernel,
                         cudaFuncAttributeMaxDynamicSharedMemorySize, SM_TOTAL);
    dim3 gg(V >> 7, M >> 7);
    gemm_mma_kernel<<<gg, 256, SM_TOTAL>>>(bias, beam, blankp, M, V, D, T, CB);

    int ssm = (2 * T + T * 32) * 4;
    cudaFuncSetAttribute(scan_kernel,
                         cudaFuncAttributeMaxDynamicSharedMemorySize, ssm);
    scan_kernel<<<B, 256, ssm>>>(xl, beam, blankp, eosp, out, T, V, CB, Ly);
}